// round 12
// baseline (speedup 1.0000x reference)
#include <cuda_runtime.h>
#include <math.h>

// Problem dims
#define S  64
#define H  1024
#define V  512
#define WV 300
#define NE 512

// Persistent kernel config: 32 blocks x 512 threads.
#define RB  32
#define RC  32
#define RT  512

// Output offsets (reference return order)
#define OFF_ENTP 0
#define OFF_ACP  (S*NE)
#define OFF_ENT  (OFF_ACP + S*V)
#define OFF_ALL  (OFF_ENT + S*H)
#define OFF_ACT  (OFF_ALL + (size_t)S*NE*H)

// Scratch (device globals; no allocation allowed)
__device__ __align__(16) float g_HH[64*2048];     // dense [relu(h) | relu(hat)]
__device__ __align__(16) float g_ACd[64*512];     // dense sigmoid(ac)
__device__ __align__(16) float g_W2V[S*H];
__device__ float g_CHOICE[S*2];
__device__ float g_SCAL[S];
// u partials, p-major, double buffered: [buf][p][entity]
__device__ __align__(16) float g_PART[2][RB*NE];
__device__ __align__(128) unsigned g_cnt;          // central barrier counter
__device__ unsigned g_pad0[31];                    // keep g_cnt line private

// ---------------------------------------------------------------------------
// Single persistent kernel: GEMM phases + smalls + 64-step recurrence.
// ---------------------------------------------------------------------------
__global__ void __launch_bounds__(RT, 1) k_fused(
    const float* __restrict__ vv,
    const float* __restrict__ evin,
    const float* __restrict__ A1w, const float* __restrict__ A1b,
    const float* __restrict__ A2w, const float* __restrict__ A2b,
    const float* __restrict__ emb,
    const float* __restrict__ W1w, const float* __restrict__ W1b,
    const float* __restrict__ W2w, const float* __restrict__ W2b,
    const float* __restrict__ W3w, const float* __restrict__ W3b,
    const float* __restrict__ W4w, const float* __restrict__ W4b,
    float* __restrict__ out)
{
    int tid = threadIdx.x;
    int blk = blockIdx.x;
    int lane = tid & 31, wid = tid >> 5;

    // ---- shared ----
    __shared__ __align__(16) float Xs[32][68];
    __shared__ __align__(16) float Ws[32][68];
    __shared__ __align__(16) float s_attn[NE];
    __shared__ __align__(16) float s_pc[16][8][4];
    __shared__ __align__(16) float s_kt[RC];
    __shared__ float s_red[16];
    __shared__ float s_sum;
    __shared__ unsigned s_old;
    __shared__ float s_c0[S], s_c1[S], s_scal[S];
    __shared__ float s_ac[V];
    __shared__ float s_bf[WV];
    __shared__ float s_cl[3];

#define BAR_ARRIVE() do { \
        __syncthreads(); \
        if (tid == 0) { \
            unsigned _old; \
            asm volatile("atom.acq_rel.gpu.global.add.u32 %0, [%1], 1;" \
                         : "=r"(_old) : "l"(&g_cnt) : "memory"); \
            s_old = _old; \
        } \
    } while (0)
#define BAR_WAIT(genv) do { \
        unsigned _tgt = 32u*(unsigned)(genv); \
        if (tid < 32) { \
            __syncwarp(); \
            if (s_old != _tgt - 1u) { \
                unsigned _c; \
                do { asm volatile("ld.acquire.gpu.global.u32 %0, [%1];" \
                                  : "=r"(_c) : "l"(&g_cnt) : "memory"); \
                } while (_c < _tgt); \
            } \
        } \
        __syncthreads(); \
    } while (0)

    // ================= Phase A: [h|hat] = relu(vv @ [A1w|W1w]^T + b) ========
    // Block owns 64 N-cols (n0 = blk*64), full M=64, K=1024. 2x4 micro-tile.
    {
        int tx = tid & 15, ty = tid >> 4;   // tx: n/4, ty: m/2
        int n0 = blk * 64;
        float acc[2][4];
#pragma unroll
        for (int q = 0; q < 2; q++)
#pragma unroll
            for (int p = 0; p < 4; p++) acc[q][p] = 0.f;

        for (int kc = 0; kc < 1024; kc += 32) {
#pragma unroll
            for (int i = 0; i < 4; i++) {
                int e = tid + 512*i; int m = e >> 5, kk = e & 31;
                Xs[kk][m] = vv[m*1024 + kc + kk];
            }
#pragma unroll
            for (int i = 0; i < 4; i++) {
                int e = tid + 512*i; int nl = e >> 5, kk = e & 31;
                int n = n0 + nl;
                const float* Wp = (n < 1024) ? (A1w + (size_t)n*1024)
                                             : (W1w + (size_t)(n-1024)*1024);
                Ws[kk][nl] = Wp[kc + kk];
            }
            __syncthreads();
#pragma unroll
            for (int kk = 0; kk < 32; kk++) {
                float x0 = Xs[kk][ty*2], x1 = Xs[kk][ty*2+1];
                float w0 = Ws[kk][tx*4+0], w1 = Ws[kk][tx*4+1];
                float w2 = Ws[kk][tx*4+2], w3 = Ws[kk][tx*4+3];
                acc[0][0] += x0*w0; acc[0][1] += x0*w1; acc[0][2] += x0*w2; acc[0][3] += x0*w3;
                acc[1][0] += x1*w0; acc[1][1] += x1*w1; acc[1][2] += x1*w2; acc[1][3] += x1*w3;
            }
            __syncthreads();
        }
#pragma unroll
        for (int q = 0; q < 2; q++)
#pragma unroll
            for (int p = 0; p < 4; p++) {
                int n = n0 + tx*4 + p;
                float b = (n < 1024) ? A1b[n] : W1b[n-1024];
                g_HH[(ty*2 + q)*2048 + n] = fmaxf(acc[q][p] + b, 0.f);
            }
    }
    BAR_ARRIVE();
    BAR_WAIT(1);

    // ================= Phase B: ac = sigmoid(h @ A2w^T + A2b) ==============
    // Block owns 16 N-cols (n0 = blk*16), M=64, K=1024. 1x2 micro-tile.
    {
        int tx = tid & 7, ty = tid >> 3;    // tx: n/2, ty: m
        int n0 = blk * 16;
        float a0 = 0.f, a1 = 0.f;
        for (int kc = 0; kc < 1024; kc += 32) {
#pragma unroll
            for (int i = 0; i < 4; i++) {
                int e = tid + 512*i; int m = e >> 5, kk = e & 31;
                Xs[kk][m] = __ldcg(&g_HH[m*2048 + kc + kk]);
            }
            {
                int nl = tid >> 5, kk = tid & 31;
                if (nl < 16) Ws[kk][nl] = A2w[(size_t)(n0 + nl)*1024 + kc + kk];
            }
            __syncthreads();
#pragma unroll
            for (int kk = 0; kk < 32; kk++) {
                float x = Xs[kk][ty];
                a0 += x*Ws[kk][tx*2+0];
                a1 += x*Ws[kk][tx*2+1];
            }
            __syncthreads();
        }
        int n = n0 + tx*2;
        g_ACd[ty*512 + n+0] = __fdividef(1.f, 1.f + __expf(-(a0 + A2b[n+0])));
        g_ACd[ty*512 + n+1] = __fdividef(1.f, 1.f + __expf(-(a1 + A2b[n+1])));
    }
    BAR_ARRIVE();
    BAR_WAIT(2);

    // ============ Phase C: w2v = [relu(hat)|sig(ac)] @ W2w^T + W2b =========
    // Block owns 32 N-cols (n0 = blk*32), M=64, K=1536. 2x2 micro-tile.
    {
        int tx = tid & 15, ty = tid >> 4;   // tx: n/2, ty: m/2
        int n0 = blk * 32;
        float a00 = 0.f, a01 = 0.f, a10 = 0.f, a11 = 0.f;
        for (int kc = 0; kc < 1536; kc += 32) {
#pragma unroll
            for (int i = 0; i < 4; i++) {
                int e = tid + 512*i; int m = e >> 5, kk = e & 31;
                int k = kc + kk;
                Xs[kk][m] = (k < 1024) ? __ldcg(&g_HH[m*2048 + 1024 + k])
                                       : __ldcg(&g_ACd[m*512 + (k - 1024)]);
            }
#pragma unroll
            for (int i = 0; i < 2; i++) {
                int e = tid + 512*i; int nl = e >> 5, kk = e & 31;
                Ws[kk][nl] = W2w[(size_t)(n0 + nl)*1536 + kc + kk];
            }
            __syncthreads();
#pragma unroll
            for (int kk = 0; kk < 32; kk++) {
                float x0 = Xs[kk][ty*2], x1 = Xs[kk][ty*2+1];
                float w0 = Ws[kk][tx*2], w1 = Ws[kk][tx*2+1];
                a00 += x0*w0; a01 += x0*w1;
                a10 += x1*w0; a11 += x1*w1;
            }
            __syncthreads();
        }
        int n = n0 + tx*2;
        g_W2V[(ty*2+0)*1024 + n+0] = a00 + W2b[n+0];
        g_W2V[(ty*2+0)*1024 + n+1] = a01 + W2b[n+1];
        g_W2V[(ty*2+1)*1024 + n+0] = a10 + W2b[n+0];
        g_W2V[(ty*2+1)*1024 + n+1] = a11 + W2b[n+1];
    }

    // ============ Phase D: smalls for steps t = blk and blk+32 =============
    for (int t = blk; t < S; t += RB) {
        float a = __ldcg(&g_ACd[t*V + tid]);
        s_ac[tid] = a;
        out[OFF_ACP + t*V + tid] = a;
        float v = a;
#pragma unroll
        for (int o = 16; o; o >>= 1) v += __shfl_xor_sync(0xffffffffu, v, o);
        if (lane == 0) s_red[wid] = v;
        __syncthreads();
        if (tid < 16) {
            float x = s_red[tid];
#pragma unroll
            for (int o = 8; o; o >>= 1) x += __shfl_xor_sync(0x0000ffffu, x, o);
            if (tid == 0) s_sum = x;
        }
        __syncthreads();
        float acsum = s_sum;

        if (tid < WV) {
            float a0 = 0.f, a1 = 0.f, a2 = 0.f, a3 = 0.f;
            for (int i = 0; i < V; i += 4) {
                a0 += s_ac[i+0]*emb[(i+0)*WV + tid];
                a1 += s_ac[i+1]*emb[(i+1)*WV + tid];
                a2 += s_ac[i+2]*emb[(i+2)*WV + tid];
                a3 += s_ac[i+3]*emb[(i+3)*WV + tid];
            }
            float bf = __fdividef((a0+a1)+(a2+a3), acsum);
            s_bf[tid] = bf;
            out[OFF_ACT + t*WV + tid] = bf;
        }
        __syncthreads();

        float p = (tid < WV) ? s_bf[tid]*W4w[tid] : 0.f;
#pragma unroll
        for (int o = 16; o; o >>= 1) p += __shfl_xor_sync(0xffffffffu, p, o);
        if (lane == 0) s_red[wid] = p;
        __syncthreads();
        if (tid < 16) {
            float x = s_red[tid];
#pragma unroll
            for (int o = 8; o; o >>= 1) x += __shfl_xor_sync(0x0000ffffu, x, o);
            if (tid == 0) g_SCAL[t] = x + W4b[0];
        }

        if (wid < 3) {
            float a3v = 0.f;
            for (int k = lane; k < H; k += 32)
                a3v += __ldcg(&g_HH[t*2048 + 1024 + k])*W3w[wid*H + k];
#pragma unroll
            for (int o = 16; o; o >>= 1) a3v += __shfl_xor_sync(0xffffffffu, a3v, o);
            if (lane == 0) s_cl[wid] = a3v + W3b[wid];
        }
        __syncthreads();
        if (tid == 0) {
            float m = fmaxf(s_cl[0], fmaxf(s_cl[1], s_cl[2]));
            float e0 = __expf(s_cl[0]-m), e1 = __expf(s_cl[1]-m), e2 = __expf(s_cl[2]-m);
            float sm = e0 + e1 + e2;
            g_CHOICE[t*2+0] = __fdividef(e0, sm);
            g_CHOICE[t*2+1] = __fdividef(e1, sm);
        }
        __syncthreads();
    }
    BAR_ARRIVE();
    BAR_WAIT(3);

    // ============ recurrence setup ============
    int g = tid & 7;          // col group (4 cols), 8 groups
    int s = tid >> 3;         // row segment (8 rows), 0..63
    int jc = blk*RC + g*4;    // first col of this thread's group
    int i0 = s*8;             // first row

    if (tid < S) {
        s_c0[tid]   = __ldcg(&g_CHOICE[tid*2+0]);
        s_c1[tid]   = __ldcg(&g_CHOICE[tid*2+1]);
        s_scal[tid] = __ldcg(&g_SCAL[tid]);
    }

    float4 evr[8];
#pragma unroll
    for (int r = 0; r < 8; r++)
        evr[r] = *(const float4*)(evin + (size_t)(i0 + r)*H + jc);

    // logit0 partials -> p-major g_PART[0][blk][*]
    {
        float4 w4 = __ldcg((const float4*)(g_W2V + jc));
        float lp[8];
#pragma unroll
        for (int r = 0; r < 8; r++)
            lp[r] = evr[r].x*w4.x + evr[r].y*w4.y + evr[r].z*w4.z + evr[r].w*w4.w;
#pragma unroll
        for (int r = 0; r < 8; r++) {
            lp[r] += __shfl_xor_sync(0xffffffffu, lp[r], 1);
            lp[r] += __shfl_xor_sync(0xffffffffu, lp[r], 2);
            lp[r] += __shfl_xor_sync(0xffffffffu, lp[r], 4);
        }
        if (g == 0) {
            *(float4*)(g_PART[0] + blk*NE + i0)     = make_float4(lp[0], lp[1], lp[2], lp[3]);
            *(float4*)(g_PART[0] + blk*NE + i0 + 4) = make_float4(lp[4], lp[5], lp[6], lp[7]);
        }
    }
    BAR_ARRIVE();
    BAR_WAIT(4);

    // ========================= 64 sequential steps =========================
    float prevE = 0.f;
    for (int t = 0; t < S; t++) {
        float c0   = s_c0[t];
        float c1   = s_c1[t];
        float scal = s_scal[t];

        const float* pp = g_PART[t & 1] + tid;
        float q0 = 0.f, q1 = 0.f, q2 = 0.f, q3 = 0.f;
#pragma unroll
        for (int bb = 0; bb < RB; bb += 4) {
            q0 += __ldcg(pp + (bb+0)*NE);
            q1 += __ldcg(pp + (bb+1)*NE);
            q2 += __ldcg(pp + (bb+2)*NE);
            q3 += __ldcg(pp + (bb+3)*NE);
        }
        float lg = (q0 + q1) + (q2 + q3);
        float ent = __fdividef(1.f, 1.f + __expf(-lg));
        float at = fmaf(c0, ent, c1*prevE);
        prevE = ent;
        s_attn[tid] = at;
        __syncthreads();

        // asum: redundant per-warp sum of s_attn (conflict-free LDS.128)
        float asum;
        {
            float4 t0 = *(const float4*)&s_attn[lane*4];
            float4 t1 = *(const float4*)&s_attn[lane*4 + 128];
            float4 t2 = *(const float4*)&s_attn[lane*4 + 256];
            float4 t3 = *(const float4*)&s_attn[lane*4 + 384];
            float v = ((t0.x+t0.y)+(t0.z+t0.w)) + ((t1.x+t1.y)+(t1.z+t1.w))
                    + ((t2.x+t2.y)+(t2.z+t2.w)) + ((t3.x+t3.y)+(t3.z+t3.w));
#pragma unroll
            for (int o = 16; o; o >>= 1) v += __shfl_xor_sync(0xffffffffu, v, o);
            asum = v;
        }

        // bar_et partial
        float4 bacc = make_float4(0.f, 0.f, 0.f, 0.f);
#pragma unroll
        for (int r = 0; r < 8; r++) {
            float a = s_attn[i0 + r];
            bacc.x = fmaf(a, evr[r].x, bacc.x);
            bacc.y = fmaf(a, evr[r].y, bacc.y);
            bacc.z = fmaf(a, evr[r].z, bacc.z);
            bacc.w = fmaf(a, evr[r].w, bacc.w);
        }
#pragma unroll
        for (int o = 8; o <= 16; o <<= 1) {
            bacc.x += __shfl_xor_sync(0xffffffffu, bacc.x, o);
            bacc.y += __shfl_xor_sync(0xffffffffu, bacc.y, o);
            bacc.z += __shfl_xor_sync(0xffffffffu, bacc.z, o);
            bacc.w += __shfl_xor_sync(0xffffffffu, bacc.w, o);
        }
        if (lane < 8) *(float4*)&s_pc[wid][lane][0] = bacc;
        __syncthreads();
        if (tid < RC) {
            int gg = tid >> 2, cc = tid & 3;
            float bs = 0.f;
#pragma unroll
            for (int w = 0; w < 16; w++) bs += s_pc[w][gg][cc];
            float bar = __fdividef(bs, asum);
            out[OFF_ENT + t*H + blk*RC + tid] = bar;
            s_kt[tid] = fmaxf(scal*bar, 0.f);
        }
        __syncthreads();
        float4 kt4 = *(const float4*)&s_kt[g*4];

        if (t < S-1) {
            float4 w4 = __ldcg((const float4*)(g_W2V + (t+1)*H + jc));
            float lp[8];
#pragma unroll
            for (int r = 0; r < 8; r++) {
                float a = s_attn[i0 + r];
                evr[r].x = fmaf(a, kt4.x - evr[r].x, evr[r].x);
                evr[r].y = fmaf(a, kt4.y - evr[r].y, evr[r].y);
                evr[r].z = fmaf(a, kt4.z - evr[r].z, evr[r].z);
                evr[r].w = fmaf(a, kt4.w - evr[r].w, evr[r].w);
                lp[r] = evr[r].x*w4.x + evr[r].y*w4.y + evr[r].z*w4.z + evr[r].w*w4.w;
            }
#pragma unroll
            for (int r = 0; r < 8; r++) {
                lp[r] += __shfl_xor_sync(0xffffffffu, lp[r], 1);
                lp[r] += __shfl_xor_sync(0xffffffffu, lp[r], 2);
                lp[r] += __shfl_xor_sync(0xffffffffu, lp[r], 4);
            }
            if (g == 0) {
                float* po = g_PART[(t+1) & 1] + blk*NE + i0;
                *(float4*)(po)     = make_float4(lp[0], lp[1], lp[2], lp[3]);
                *(float4*)(po + 4) = make_float4(lp[4], lp[5], lp[6], lp[7]);
            }

            BAR_ARRIVE();
            if (blk == 0) out[OFF_ENTP + t*NE + tid] = ent;
            {
                float* snap = out + OFF_ALL + (size_t)t*NE*H + jc;
#pragma unroll
                for (int r = 0; r < 8; r++)
                    __stcs((float4*)(snap + (size_t)(i0 + r)*H), evr[r]);
            }
            BAR_WAIT(5 + t);
        } else {
#pragma unroll
            for (int r = 0; r < 8; r++) {
                float a = s_attn[i0 + r];
                evr[r].x = fmaf(a, kt4.x - evr[r].x, evr[r].x);
                evr[r].y = fmaf(a, kt4.y - evr[r].y, evr[r].y);
                evr[r].z = fmaf(a, kt4.z - evr[r].z, evr[r].z);
                evr[r].w = fmaf(a, kt4.w - evr[r].w, evr[r].w);
            }
            if (blk == 0) out[OFF_ENTP + t*NE + tid] = ent;
            float* snap = out + OFF_ALL + (size_t)t*NE*H + jc;
#pragma unroll
            for (int r = 0; r < 8; r++)
                __stcs((float4*)(snap + (size_t)(i0 + r)*H), evr[r]);
        }
    }

    // Final arrive: last arriver resets the counter for the next graph replay.
    // Non-stragglers exit without waiting.
    __syncthreads();
    if (tid == 0) {
        unsigned old;
        asm volatile("atom.acq_rel.gpu.global.add.u32 %0, [%1], 1;"
                     : "=r"(old) : "l"(&g_cnt) : "memory");
        // gens used: 1..4 prologue, 5..67 steps (t=0..62), this arrive = gen 68
        if (old == 32u*68u - 1u) {
            asm volatile("st.release.gpu.global.u32 [%0], %1;"
                         :: "l"(&g_cnt), "r"(0u) : "memory");
        }
    }
#undef BAR_ARRIVE
#undef BAR_WAIT
}

// ---------------------------------------------------------------------------
extern "C" void kernel_launch(void* const* d_in, const int* in_sizes, int n_in,
                              void* d_out, int out_size)
{
    (void)in_sizes; (void)n_in; (void)out_size;
    const float* vv  = (const float*)d_in[0];
    const float* ev  = (const float*)d_in[1];
    const float* A1w = (const float*)d_in[2];
    const float* A1b = (const float*)d_in[3];
    const float* A2w = (const float*)d_in[4];
    const float* A2b = (const float*)d_in[5];
    const float* emb = (const float*)d_in[6];
    const float* W1w = (const float*)d_in[7];
    const float* W1b = (const float*)d_in[8];
    const float* W2w = (const float*)d_in[9];
    const float* W2b = (const float*)d_in[10];
    const float* W3w = (const float*)d_in[11];
    const float* W3b = (const float*)d_in[12];
    const float* W4w = (const float*)d_in[13];
    const float* W4b = (const float*)d_in[14];
    float* out = (float*)d_out;

    k_fused<<<RB, RT>>>(vv, ev, A1w, A1b, A2w, A2b, emb,
                        W1w, W1b, W2w, W2b, W3w, W3b, W4w, W4b, out);
}